// round 1
// baseline (speedup 1.0000x reference)
#include <cuda_runtime.h>
#include <math.h>

#define BSZ 2
#define SEQ 2048
#define EMB 2048
#define NH  16
#define HD  128
#define E3  (3*EMB)
#define ROWS (BSZ*SEQ)           // 4096
#define SCALE 0.08838834764831845f   // 1/sqrt(128)

// ---------------- scratch (static device memory; no allocations) ----------
__device__ float g_qkv[(size_t)BSZ * SEQ * E3];    // [B,N,3E]  ~96 MB
__device__ float g_attn[(size_t)BSZ * SEQ * EMB];  // [B,N,E]   ~32 MB

// ---------------- packed f32x2 helpers (sm_103a) --------------------------
__device__ __forceinline__ unsigned long long pack2(float lo, float hi) {
    unsigned long long r;
    asm("mov.b64 %0, {%1, %2};" : "=l"(r) : "f"(lo), "f"(hi));
    return r;
}
__device__ __forceinline__ void fma2(unsigned long long& d,
                                     unsigned long long a,
                                     unsigned long long b) {
    asm("fma.rn.f32x2 %0, %1, %2, %0;" : "+l"(d) : "l"(a), "l"(b));
}
__device__ __forceinline__ float2 unpack2(unsigned long long v) {
    float2 f;
    asm("mov.b64 {%0, %1}, %2;" : "=f"(f.x), "=f"(f.y) : "l"(v));
    return f;
}

// ===========================================================================
// Generic NN SGEMM: C[M,Ncol] = A[M,K] * B[K,Ncol] (+bias), 128x128x16 tiles,
// 256 threads, 8x8 microtile, f32x2 FMA accumulation.
// ===========================================================================
template <bool BIAS>
__global__ __launch_bounds__(256)
void sgemm_nn(const float* __restrict__ A, const float* __restrict__ B,
              float* __restrict__ C, int K,
              int lda, int ldb, int ldc, const float* __restrict__ bias)
{
    __shared__ float As[16][128];   // As[k][m]
    __shared__ float Bs[16][128];   // Bs[k][n]

    const int tid = threadIdx.x;
    const int tx  = tid & 15;
    const int ty  = tid >> 4;
    const int m0  = blockIdx.y * 128;
    const int n0  = blockIdx.x * 128;

    unsigned long long acc[8][4];
#pragma unroll
    for (int i = 0; i < 8; i++)
#pragma unroll
        for (int j = 0; j < 4; j++) acc[i][j] = 0ULL;

    for (int k0 = 0; k0 < K; k0 += 16) {
        // A tile: 128 rows x 16 cols, transposed into As[k][m]
#pragma unroll
        for (int s = 0; s < 2; s++) {
            int f   = tid * 2 + s;         // 0..511 float4s
            int row = f >> 2;              // 4 float4 per row
            int cg  = (f & 3) * 4;
            float4 v = *reinterpret_cast<const float4*>(
                A + (size_t)(m0 + row) * lda + k0 + cg);
            As[cg + 0][row] = v.x; As[cg + 1][row] = v.y;
            As[cg + 2][row] = v.z; As[cg + 3][row] = v.w;
        }
        // B tile: 16 rows x 128 cols, direct
#pragma unroll
        for (int s = 0; s < 2; s++) {
            int f   = tid * 2 + s;
            int row = f >> 5;              // 32 float4 per row
            int cg  = (f & 31) * 4;
            *reinterpret_cast<float4*>(&Bs[row][cg]) =
                *reinterpret_cast<const float4*>(
                    B + (size_t)(k0 + row) * ldb + n0 + cg);
        }
        __syncthreads();
#pragma unroll
        for (int k = 0; k < 16; k++) {
            float4 a0 = *reinterpret_cast<const float4*>(&As[k][ty * 8]);
            float4 a1 = *reinterpret_cast<const float4*>(&As[k][ty * 8 + 4]);
            float4 b0 = *reinterpret_cast<const float4*>(&Bs[k][tx * 8]);
            float4 b1 = *reinterpret_cast<const float4*>(&Bs[k][tx * 8 + 4]);
            float a[8] = {a0.x, a0.y, a0.z, a0.w, a1.x, a1.y, a1.z, a1.w};
            unsigned long long b2[4];
            b2[0] = pack2(b0.x, b0.y); b2[1] = pack2(b0.z, b0.w);
            b2[2] = pack2(b1.x, b1.y); b2[3] = pack2(b1.z, b1.w);
#pragma unroll
            for (int i = 0; i < 8; i++) {
                unsigned long long a2 = pack2(a[i], a[i]);
#pragma unroll
                for (int jp = 0; jp < 4; jp++) fma2(acc[i][jp], a2, b2[jp]);
            }
        }
        __syncthreads();
    }
#pragma unroll
    for (int i = 0; i < 8; i++) {
        int row = m0 + ty * 8 + i;
#pragma unroll
        for (int jp = 0; jp < 4; jp++) {
            int col = n0 + tx * 8 + jp * 2;
            float2 v = unpack2(acc[i][jp]);
            if (BIAS) { v.x += bias[col]; v.y += bias[col + 1]; }
            *reinterpret_cast<float2*>(C + (size_t)row * ldc + col) = v;
        }
    }
}

// ===========================================================================
// Scores: S[bh][n][m] = (Q[n]·K[m]) * SCALE for m<=n else -inf
// Q,K live inside g_qkv (lda/ldb = 3E). Fully-masked tiles skip compute.
// ===========================================================================
__global__ __launch_bounds__(256)
void scores_kernel(float* __restrict__ Sout)
{
    const int bh = blockIdx.z;
    const int b  = bh / NH, h = bh % NH;
    const float* Q  = g_qkv + (size_t)b * SEQ * E3 + h * HD;
    const float* Km = g_qkv + (size_t)b * SEQ * E3 + EMB + h * HD;
    float* S = Sout + (size_t)bh * SEQ * SEQ;

    const int tid = threadIdx.x;
    const int tx  = tid & 15;
    const int ty  = tid >> 4;
    const int n0  = blockIdx.y * 128;   // query rows
    const int m0  = blockIdx.x * 128;   // key cols

    const float NEG_INF = __int_as_float(0xff800000);

    if (m0 > n0 + 127) {   // fully masked tile: write -inf only
        float4 NI = make_float4(NEG_INF, NEG_INF, NEG_INF, NEG_INF);
#pragma unroll
        for (int i = 0; i < 8; i++) {
            int row = n0 + ty * 8 + i;
            *reinterpret_cast<float4*>(S + (size_t)row * SEQ + m0 + tx * 8) = NI;
            *reinterpret_cast<float4*>(S + (size_t)row * SEQ + m0 + tx * 8 + 4) = NI;
        }
        return;
    }

    __shared__ float Qs[16][128];   // Qs[d][n]
    __shared__ float Ks[16][128];   // Ks[d][m]

    unsigned long long acc[8][4];
#pragma unroll
    for (int i = 0; i < 8; i++)
#pragma unroll
        for (int j = 0; j < 4; j++) acc[i][j] = 0ULL;

    for (int d0 = 0; d0 < HD; d0 += 16) {
#pragma unroll
        for (int s = 0; s < 2; s++) {
            int f   = tid * 2 + s;
            int row = f >> 2;
            int cg  = (f & 3) * 4;
            float4 q = *reinterpret_cast<const float4*>(
                Q + (size_t)(n0 + row) * E3 + d0 + cg);
            Qs[cg + 0][row] = q.x; Qs[cg + 1][row] = q.y;
            Qs[cg + 2][row] = q.z; Qs[cg + 3][row] = q.w;
            float4 kk = *reinterpret_cast<const float4*>(
                Km + (size_t)(m0 + row) * E3 + d0 + cg);
            Ks[cg + 0][row] = kk.x; Ks[cg + 1][row] = kk.y;
            Ks[cg + 2][row] = kk.z; Ks[cg + 3][row] = kk.w;
        }
        __syncthreads();
#pragma unroll
        for (int k = 0; k < 16; k++) {
            float4 a0 = *reinterpret_cast<const float4*>(&Qs[k][ty * 8]);
            float4 a1 = *reinterpret_cast<const float4*>(&Qs[k][ty * 8 + 4]);
            float4 b0 = *reinterpret_cast<const float4*>(&Ks[k][tx * 8]);
            float4 b1 = *reinterpret_cast<const float4*>(&Ks[k][tx * 8 + 4]);
            float a[8] = {a0.x, a0.y, a0.z, a0.w, a1.x, a1.y, a1.z, a1.w};
            unsigned long long b2[4];
            b2[0] = pack2(b0.x, b0.y); b2[1] = pack2(b0.z, b0.w);
            b2[2] = pack2(b1.x, b1.y); b2[3] = pack2(b1.z, b1.w);
#pragma unroll
            for (int i = 0; i < 8; i++) {
                unsigned long long a2 = pack2(a[i], a[i]);
#pragma unroll
                for (int jp = 0; jp < 4; jp++) fma2(acc[i][jp], a2, b2[jp]);
            }
        }
        __syncthreads();
    }
#pragma unroll
    for (int i = 0; i < 8; i++) {
        int row = n0 + ty * 8 + i;
#pragma unroll
        for (int jp = 0; jp < 4; jp++) {
            int col = m0 + tx * 8 + jp * 2;
            float2 v = unpack2(acc[i][jp]);
            v.x = (col     <= row) ? v.x * SCALE : NEG_INF;
            v.y = (col + 1 <= row) ? v.y * SCALE : NEG_INF;
            *reinterpret_cast<float2*>(S + (size_t)row * SEQ + col) = v;
        }
    }
}

// ===========================================================================
// Row softmax in place over the attn_weights region. One block per row.
// ===========================================================================
__global__ __launch_bounds__(256)
void softmax_kernel(float* __restrict__ P)
{
    float* p = P + (size_t)blockIdx.x * SEQ;
    const int tid = threadIdx.x;
    float4* p4 = reinterpret_cast<float4*>(p);

    float4 v0 = p4[tid];
    float4 v1 = p4[tid + 256];

    float m = fmaxf(fmaxf(fmaxf(v0.x, v0.y), fmaxf(v0.z, v0.w)),
                    fmaxf(fmaxf(v1.x, v1.y), fmaxf(v1.z, v1.w)));

    __shared__ float red[256];
    red[tid] = m; __syncthreads();
    for (int s = 128; s > 0; s >>= 1) {
        if (tid < s) red[tid] = fmaxf(red[tid], red[tid + s]);
        __syncthreads();
    }
    float rmax = red[0];
    __syncthreads();

    v0.x = __expf(v0.x - rmax); v0.y = __expf(v0.y - rmax);
    v0.z = __expf(v0.z - rmax); v0.w = __expf(v0.w - rmax);
    v1.x = __expf(v1.x - rmax); v1.y = __expf(v1.y - rmax);
    v1.z = __expf(v1.z - rmax); v1.w = __expf(v1.w - rmax);

    float ssum = v0.x + v0.y + v0.z + v0.w + v1.x + v1.y + v1.z + v1.w;
    red[tid] = ssum; __syncthreads();
    for (int s = 128; s > 0; s >>= 1) {
        if (tid < s) red[tid] += red[tid + s];
        __syncthreads();
    }
    float inv = 1.0f / red[0];

    v0.x *= inv; v0.y *= inv; v0.z *= inv; v0.w *= inv;
    v1.x *= inv; v1.y *= inv; v1.z *= inv; v1.w *= inv;
    p4[tid] = v0;
    p4[tid + 256] = v1;
}

// ===========================================================================
// PV: attn_out[b, n, h*HD + d] = sum_m P[bh][n][m] * V[b, m, h*HD + d]
// Causal k-limit: rows of P past m > n0+127 are zero -> stop k there.
// ===========================================================================
__global__ __launch_bounds__(256)
void sgemm_pv(const float* __restrict__ Pw)
{
    const int bh = blockIdx.z;
    const int b  = bh / NH, h = bh % NH;
    const float* A  = Pw + (size_t)bh * SEQ * SEQ;                    // lda = SEQ
    const float* Bv = g_qkv + (size_t)b * SEQ * E3 + 2 * EMB + h * HD; // ldb = E3
    float* C = g_attn + (size_t)b * SEQ * EMB + h * HD;               // ldc = EMB

    __shared__ float As[16][128];
    __shared__ float Bs[16][128];

    const int tid = threadIdx.x;
    const int tx  = tid & 15;
    const int ty  = tid >> 4;
    const int r0  = blockIdx.y * 128;     // query-row tile
    const int kmax = r0 + 128;            // causal limit

    unsigned long long acc[8][4];
#pragma unroll
    for (int i = 0; i < 8; i++)
#pragma unroll
        for (int j = 0; j < 4; j++) acc[i][j] = 0ULL;

    for (int k0 = 0; k0 < kmax; k0 += 16) {
#pragma unroll
        for (int s = 0; s < 2; s++) {
            int f   = tid * 2 + s;
            int row = f >> 2;
            int cg  = (f & 3) * 4;
            float4 v = *reinterpret_cast<const float4*>(
                A + (size_t)(r0 + row) * SEQ + k0 + cg);
            As[cg + 0][row] = v.x; As[cg + 1][row] = v.y;
            As[cg + 2][row] = v.z; As[cg + 3][row] = v.w;
        }
#pragma unroll
        for (int s = 0; s < 2; s++) {
            int f   = tid * 2 + s;
            int row = f >> 5;
            int cg  = (f & 31) * 4;
            *reinterpret_cast<float4*>(&Bs[row][cg]) =
                *reinterpret_cast<const float4*>(
                    Bv + (size_t)(k0 + row) * E3 + cg);
        }
        __syncthreads();
#pragma unroll
        for (int k = 0; k < 16; k++) {
            float4 a0 = *reinterpret_cast<const float4*>(&As[k][ty * 8]);
            float4 a1 = *reinterpret_cast<const float4*>(&As[k][ty * 8 + 4]);
            float4 b0 = *reinterpret_cast<const float4*>(&Bs[k][tx * 8]);
            float4 b1 = *reinterpret_cast<const float4*>(&Bs[k][tx * 8 + 4]);
            float a[8] = {a0.x, a0.y, a0.z, a0.w, a1.x, a1.y, a1.z, a1.w};
            unsigned long long b2[4];
            b2[0] = pack2(b0.x, b0.y); b2[1] = pack2(b0.z, b0.w);
            b2[2] = pack2(b1.x, b1.y); b2[3] = pack2(b1.z, b1.w);
#pragma unroll
            for (int i = 0; i < 8; i++) {
                unsigned long long a2 = pack2(a[i], a[i]);
#pragma unroll
                for (int jp = 0; jp < 4; jp++) fma2(acc[i][jp], a2, b2[jp]);
            }
        }
        __syncthreads();
    }
#pragma unroll
    for (int i = 0; i < 8; i++) {
        int row = r0 + ty * 8 + i;
#pragma unroll
        for (int jp = 0; jp < 4; jp++) {
            int col = tx * 8 + jp * 2;
            float2 v = unpack2(acc[i][jp]);
            *reinterpret_cast<float2*>(C + (size_t)row * EMB + col) = v;
        }
    }
}

// ===========================================================================
extern "C" void kernel_launch(void* const* d_in, const int* in_sizes, int n_in,
                              void* d_out, int out_size)
{
    (void)in_sizes; (void)n_in; (void)out_size;
    const float* hidden  = (const float*)d_in[0];   // [B,N,E]
    const float* w_fused = (const float*)d_in[1];   // [E,3E]
    const float* w_proj  = (const float*)d_in[2];   // [E,E]
    const float* b_proj  = (const float*)d_in[3];   // [E]

    float* out   = (float*)d_out;                       // [B,N,E]
    float* attnw = out + (size_t)ROWS * EMB;            // [B,H,N,N]

    float* qkv  = nullptr;
    float* attn = nullptr;
    cudaGetSymbolAddress((void**)&qkv,  g_qkv);
    cudaGetSymbolAddress((void**)&attn, g_attn);
    (void)qkv; (void)attn;   // kernels reference the globals directly

    // 1) qkv = hidden @ w_fused      [4096,2048]x[2048,6144]
    sgemm_nn<false><<<dim3(E3 / 128, ROWS / 128), 256>>>(
        hidden, w_fused, qkv, EMB, EMB, E3, E3, nullptr);

    // 2) scores (masked) -> attn_weights region of d_out
    scores_kernel<<<dim3(SEQ / 128, SEQ / 128, BSZ * NH), 256>>>(attnw);

    // 3) softmax rows in place
    softmax_kernel<<<BSZ * NH * SEQ, 256>>>(attnw);

    // 4) attn_out = P @ V
    sgemm_pv<<<dim3(1, SEQ / 128, BSZ * NH), 256>>>(attnw);

    // 5) out = attn_out @ w_proj + b_proj
    sgemm_nn<true><<<dim3(EMB / 128, ROWS / 128), 256>>>(
        attn, w_proj, out, EMB, EMB, EMB, EMB, b_proj);
}

// round 3
// speedup vs baseline: 2.6538x; 2.6538x over previous
#include <cuda_runtime.h>
#include <cuda_bf16.h>
#include <cstdint>

#define BSZ 2
#define SEQ 2048
#define EMB 2048
#define NH  16
#define HD  128
#define E3  (3*EMB)
#define ROWS (BSZ*SEQ)
#define SCALE 0.08838834764831845f

// ---------------- static device scratch (no allocations) ------------------
__device__ float g_qkv[(size_t)ROWS * E3];                       // [B,N,3E] fp32
__device__ float g_attn[(size_t)ROWS * EMB];                     // [B,N,E]  fp32
__device__ __nv_bfloat16 g_wfT_hi[(size_t)E3 * EMB];             // w_fused^T hi
__device__ __nv_bfloat16 g_wfT_lo[(size_t)E3 * EMB];             // w_fused^T lo
__device__ __nv_bfloat16 g_wpT_hi[(size_t)EMB * EMB];            // w_proj^T hi
__device__ __nv_bfloat16 g_wpT_lo[(size_t)EMB * EMB];            // w_proj^T lo
__device__ __nv_bfloat16 g_vt_hi[(size_t)BSZ * NH * HD * SEQ];   // V^T per head hi
__device__ __nv_bfloat16 g_vt_lo[(size_t)BSZ * NH * HD * SEQ];   // V^T per head lo

// ---------------- smem layout: 4 tiles of 128 rows x 72 bf16 (padded 64) --
#define TSTR 72                       // row stride in bf16 elems (144 B)
#define TILE_B (128 * TSTR * 2)       // 18432 bytes
#define SM_AHI 0
#define SM_ALO (TILE_B)
#define SM_BHI (2 * TILE_B)
#define SM_BLO (3 * TILE_B)
#define SM_TOTAL (4 * TILE_B)         // 73728

__device__ __forceinline__ uint32_t smem_u32(const void* p) {
    uint32_t a;
    asm("{ .reg .u64 t; cvta.to.shared.u64 t, %1; cvt.u32.u64 %0, t; }"
        : "=r"(a) : "l"(p));
    return a;
}
__device__ __forceinline__ void sts64(uint32_t a, uint32_t x, uint32_t y) {
    asm volatile("st.shared.v2.u32 [%0], {%1,%2};" :: "r"(a), "r"(x), "r"(y) : "memory");
}
__device__ __forceinline__ void sts128(uint32_t a, uint4 v) {
    asm volatile("st.shared.v4.u32 [%0], {%1,%2,%3,%4};"
                 :: "r"(a), "r"(v.x), "r"(v.y), "r"(v.z), "r"(v.w) : "memory");
}

#define LDMX4(r, a)                                                          \
    asm volatile("ldmatrix.sync.aligned.m8n8.x4.shared.b16 {%0,%1,%2,%3}, [%4];" \
                 : "=r"((r)[0]), "=r"((r)[1]), "=r"((r)[2]), "=r"((r)[3]) : "r"(a))

#define MMA16816(d, a, b0v, b1v)                                             \
    asm volatile("mma.sync.aligned.m16n8k16.row.col.f32.bf16.bf16.f32 "      \
                 "{%0,%1,%2,%3}, {%4,%5,%6,%7}, {%8,%9}, {%0,%1,%2,%3};"     \
                 : "+f"((d)[0]), "+f"((d)[1]), "+f"((d)[2]), "+f"((d)[3])    \
                 : "r"((a)[0]), "r"((a)[1]), "r"((a)[2]), "r"((a)[3]),       \
                   "r"(b0v), "r"(b1v))

// ---- global -> smem loaders ------------------------------------------------
// 128x64 fp32 tile -> hi/lo bf16 (truncate-split), padded rows
__device__ __forceinline__ void load_f32_hl(const float* __restrict__ src, int ld,
                                            uint32_t dHi, uint32_t dLo, int tid) {
#pragma unroll
    for (int i = 0; i < 8; i++) {
        int f = tid + i * 256;        // 0..2047 float4s
        int row = f >> 4, kg = (f & 15) * 4;
        float4 v = *reinterpret_cast<const float4*>(src + (size_t)row * ld + kg);
        uint32_t b0 = __float_as_uint(v.x), b1 = __float_as_uint(v.y);
        uint32_t b2 = __float_as_uint(v.z), b3 = __float_as_uint(v.w);
        uint32_t hi01 = __byte_perm(b0, b1, 0x7632);
        uint32_t hi23 = __byte_perm(b2, b3, 0x7632);
        float l0 = v.x - __uint_as_float(b0 & 0xFFFF0000u);
        float l1 = v.y - __uint_as_float(b1 & 0xFFFF0000u);
        float l2 = v.z - __uint_as_float(b2 & 0xFFFF0000u);
        float l3 = v.w - __uint_as_float(b3 & 0xFFFF0000u);
        __nv_bfloat162 p01 = __floats2bfloat162_rn(l0, l1);
        __nv_bfloat162 p23 = __floats2bfloat162_rn(l2, l3);
        uint32_t off = (uint32_t)(row * TSTR + kg) * 2;
        sts64(dHi + off, hi01, hi23);
        sts64(dLo + off, *reinterpret_cast<uint32_t*>(&p01),
                          *reinterpret_cast<uint32_t*>(&p23));
    }
}
// 128x64 pre-split bf16 tiles ([n][k] row-major, ld elems)
__device__ __forceinline__ void load_b16(const __nv_bfloat16* __restrict__ hi,
                                         const __nv_bfloat16* __restrict__ lo, int ld,
                                         uint32_t dHi, uint32_t dLo, int tid) {
#pragma unroll
    for (int i = 0; i < 4; i++) {
        int f = tid + i * 256;        // 0..1023 uint4s
        int row = f >> 3, kg = (f & 7) * 8;
        uint4 vh = *reinterpret_cast<const uint4*>(hi + (size_t)row * ld + kg);
        uint4 vl = *reinterpret_cast<const uint4*>(lo + (size_t)row * ld + kg);
        uint32_t off = (uint32_t)(row * TSTR + kg) * 2;
        sts128(dHi + off, vh);
        sts128(dLo + off, vl);
    }
}

// ---- per-chunk compute: warp tile 32(m) x 64(n), K=64, 3-pass split -------
__device__ __forceinline__ void mma_chunk(uint32_t sb, int warp_m, int warp_n,
                                          int lane, float acc[2][8][4]) {
    const int arow = (lane & 7) + ((lane >> 3) & 1) * 8;
    const int acol = (lane >> 4) * 8;
    const int brow = (lane & 7) + (lane >> 4) * 8;
    const int bcol = ((lane >> 3) & 1) * 8;
#pragma unroll
    for (int k16 = 0; k16 < 4; k16++) {
        const int k0 = k16 * 16;
        uint32_t ah[2][4], al[2][4];
#pragma unroll
        for (int mt = 0; mt < 2; mt++) {
            uint32_t a = sb + SM_AHI +
                (uint32_t)((warp_m * 32 + mt * 16 + arow) * TSTR + k0 + acol) * 2;
            LDMX4(ah[mt], a);
            LDMX4(al[mt], a + (SM_ALO - SM_AHI));
        }
#pragma unroll
        for (int np = 0; np < 4; np++) {
            uint32_t b = sb + SM_BHI +
                (uint32_t)((warp_n * 64 + np * 16 + brow) * TSTR + k0 + bcol) * 2;
            uint32_t bh[4], bl[4];
            LDMX4(bh, b);
            LDMX4(bl, b + (SM_BLO - SM_BHI));
#pragma unroll
            for (int mt = 0; mt < 2; mt++) {
                MMA16816(acc[mt][2 * np],     ah[mt], bh[0], bh[1]);
                MMA16816(acc[mt][2 * np + 1], ah[mt], bh[2], bh[3]);
                MMA16816(acc[mt][2 * np],     ah[mt], bl[0], bl[1]);
                MMA16816(acc[mt][2 * np + 1], ah[mt], bl[2], bl[3]);
                MMA16816(acc[mt][2 * np],     al[mt], bh[0], bh[1]);
                MMA16816(acc[mt][2 * np + 1], al[mt], bh[2], bh[3]);
            }
        }
    }
}

#define GEMM_DECL()                                                          \
    extern __shared__ char smc[];                                            \
    uint32_t sb = smem_u32(smc);                                             \
    const int tid = threadIdx.x;                                             \
    const int wid = tid >> 5, lane = tid & 31;                               \
    const int warp_m = wid & 3, warp_n = wid >> 2;                           \
    float acc[2][8][4];                                                      \
    _Pragma("unroll") for (int i = 0; i < 2; i++)                            \
    _Pragma("unroll") for (int j = 0; j < 8; j++)                            \
    _Pragma("unroll") for (int q = 0; q < 4; q++) acc[i][j][q] = 0.0f;

// ===========================================================================
__global__ __launch_bounds__(256, 2) void gemm_qkv(const float* __restrict__ A) {
    GEMM_DECL();
    const int m0 = blockIdx.y * 128, n0 = blockIdx.x * 128;
    const float* a = A + (size_t)m0 * EMB;
    const __nv_bfloat16* bh = g_wfT_hi + (size_t)n0 * EMB;
    const __nv_bfloat16* bl = g_wfT_lo + (size_t)n0 * EMB;
    for (int c = 0; c < EMB / 64; c++) {
        load_f32_hl(a + c * 64, EMB, sb + SM_AHI, sb + SM_ALO, tid);
        load_b16(bh + c * 64, bl + c * 64, EMB, sb + SM_BHI, sb + SM_BLO, tid);
        __syncthreads();
        mma_chunk(sb, warp_m, warp_n, lane, acc);
        __syncthreads();
    }
    const int g = lane >> 2, t = lane & 3;
#pragma unroll
    for (int mt = 0; mt < 2; mt++)
#pragma unroll
        for (int nt = 0; nt < 8; nt++) {
            int r = m0 + warp_m * 32 + mt * 16 + g;
            int c = n0 + warp_n * 64 + nt * 8 + t * 2;
            *reinterpret_cast<float2*>(g_qkv + (size_t)r * E3 + c) =
                make_float2(acc[mt][nt][0], acc[mt][nt][1]);
            *reinterpret_cast<float2*>(g_qkv + (size_t)(r + 8) * E3 + c) =
                make_float2(acc[mt][nt][2], acc[mt][nt][3]);
        }
}

// ===========================================================================
__global__ __launch_bounds__(256, 2) void gemm_scores(float* __restrict__ S) {
    const int bh2 = blockIdx.z, b = bh2 >> 4, h = bh2 & 15;
    const int m0 = blockIdx.x * 128;   // key cols
    const int n0 = blockIdx.y * 128;   // query rows
    float* out = S + (size_t)bh2 * SEQ * SEQ;
    const float NEG_INF = __int_as_float(0xff800000);
    if (m0 > n0 + 127) {               // fully masked tile
        const int t = threadIdx.x;
        float4 NI = make_float4(NEG_INF, NEG_INF, NEG_INF, NEG_INF);
#pragma unroll
        for (int i = 0; i < 16; i++) {
            int f = t + i * 256;
            int row = f >> 5, gq = f & 31;
            *reinterpret_cast<float4*>(out + (size_t)(n0 + row) * SEQ + m0 + gq * 4) = NI;
        }
        return;
    }
    GEMM_DECL();
    const float* q  = g_qkv + (size_t)b * SEQ * E3 + h * HD + (size_t)n0 * E3;
    const float* kk = g_qkv + (size_t)b * SEQ * E3 + EMB + h * HD + (size_t)m0 * E3;
    for (int c = 0; c < 2; c++) {
        load_f32_hl(q + c * 64, E3, sb + SM_AHI, sb + SM_ALO, tid);
        load_f32_hl(kk + c * 64, E3, sb + SM_BHI, sb + SM_BLO, tid);
        __syncthreads();
        mma_chunk(sb, warp_m, warp_n, lane, acc);
        __syncthreads();
    }
    const int g = lane >> 2, t = lane & 3;
#pragma unroll
    for (int mt = 0; mt < 2; mt++)
#pragma unroll
        for (int nt = 0; nt < 8; nt++) {
            int r = n0 + warp_m * 32 + mt * 16 + g;
            int c = m0 + warp_n * 64 + nt * 8 + t * 2;
            float2 v0, v1;
            v0.x = (c     <= r) ? acc[mt][nt][0] * SCALE : NEG_INF;
            v0.y = (c + 1 <= r) ? acc[mt][nt][1] * SCALE : NEG_INF;
            v1.x = (c     <= r + 8) ? acc[mt][nt][2] * SCALE : NEG_INF;
            v1.y = (c + 1 <= r + 8) ? acc[mt][nt][3] * SCALE : NEG_INF;
            *reinterpret_cast<float2*>(out + (size_t)r * SEQ + c) = v0;
            *reinterpret_cast<float2*>(out + (size_t)(r + 8) * SEQ + c) = v1;
        }
}

// ===========================================================================
__global__ __launch_bounds__(256, 2) void gemm_pv(const float* __restrict__ P) {
    GEMM_DECL();
    const int bh2 = blockIdx.z, b = bh2 >> 4, h = bh2 & 15;
    const int n0 = blockIdx.y * 128;   // query-row tile
    const float* a = P + (size_t)bh2 * SEQ * SEQ + (size_t)n0 * SEQ;
    const __nv_bfloat16* vh = g_vt_hi + (size_t)bh2 * HD * SEQ;
    const __nv_bfloat16* vl = g_vt_lo + (size_t)bh2 * HD * SEQ;
    const int nch = (n0 + 128) >> 6;   // causal K limit
    for (int c = 0; c < nch; c++) {
        load_f32_hl(a + c * 64, SEQ, sb + SM_AHI, sb + SM_ALO, tid);
        load_b16(vh + c * 64, vl + c * 64, SEQ, sb + SM_BHI, sb + SM_BLO, tid);
        __syncthreads();
        mma_chunk(sb, warp_m, warp_n, lane, acc);
        __syncthreads();
    }
    const int g = lane >> 2, t = lane & 3;
#pragma unroll
    for (int mt = 0; mt < 2; mt++)
#pragma unroll
        for (int nt = 0; nt < 8; nt++) {
            int r = n0 + warp_m * 32 + mt * 16 + g;
            int c = warp_n * 64 + nt * 8 + t * 2;
            float* dst = g_attn + (size_t)(b * SEQ + r) * EMB + h * HD + c;
            *reinterpret_cast<float2*>(dst) =
                make_float2(acc[mt][nt][0], acc[mt][nt][1]);
            *reinterpret_cast<float2*>(dst + (size_t)8 * EMB) =
                make_float2(acc[mt][nt][2], acc[mt][nt][3]);
        }
}

// ===========================================================================
__global__ __launch_bounds__(256, 2) void gemm_proj(float* __restrict__ C,
                                                    const float* __restrict__ bias) {
    GEMM_DECL();
    const int m0 = blockIdx.y * 128, n0 = blockIdx.x * 128;
    const float* a = g_attn + (size_t)m0 * EMB;
    const __nv_bfloat16* bh = g_wpT_hi + (size_t)n0 * EMB;
    const __nv_bfloat16* bl = g_wpT_lo + (size_t)n0 * EMB;
    for (int c = 0; c < EMB / 64; c++) {
        load_f32_hl(a + c * 64, EMB, sb + SM_AHI, sb + SM_ALO, tid);
        load_b16(bh + c * 64, bl + c * 64, EMB, sb + SM_BHI, sb + SM_BLO, tid);
        __syncthreads();
        mma_chunk(sb, warp_m, warp_n, lane, acc);
        __syncthreads();
    }
    const int g = lane >> 2, t = lane & 3;
#pragma unroll
    for (int mt = 0; mt < 2; mt++)
#pragma unroll
        for (int nt = 0; nt < 8; nt++) {
            int r = m0 + warp_m * 32 + mt * 16 + g;
            int c = n0 + warp_n * 64 + nt * 8 + t * 2;
            float2 bv = *reinterpret_cast<const float2*>(bias + c);
            *reinterpret_cast<float2*>(C + (size_t)r * EMB + c) =
                make_float2(acc[mt][nt][0] + bv.x, acc[mt][nt][1] + bv.y);
            *reinterpret_cast<float2*>(C + (size_t)(r + 8) * EMB + c) =
                make_float2(acc[mt][nt][2] + bv.x, acc[mt][nt][3] + bv.y);
        }
}

// ===========================================================================
// Transpose + bf16 hi/lo split: in [rows, cols] -> out [cols, rows]
__global__ void transpose_hl(const float* __restrict__ in, int rows, int cols,
                             __nv_bfloat16* __restrict__ oh, __nv_bfloat16* __restrict__ ol) {
    __shared__ float t[32][33];
    int c0 = blockIdx.x * 32, r0 = blockIdx.y * 32;
    int tx = threadIdx.x, ty = threadIdx.y;
#pragma unroll
    for (int j = 0; j < 32; j += 8)
        t[ty + j][tx] = in[(size_t)(r0 + ty + j) * cols + c0 + tx];
    __syncthreads();
#pragma unroll
    for (int j = 0; j < 32; j += 8) {
        float v = t[tx][ty + j];
        uint32_t bits = __float_as_uint(v);
        __nv_bfloat16 h = __ushort_as_bfloat16((unsigned short)(bits >> 16));
        __nv_bfloat16 l = __float2bfloat16(v - __uint_as_float(bits & 0xFFFF0000u));
        size_t o = (size_t)(c0 + ty + j) * rows + r0 + tx;
        oh[o] = h; ol[o] = l;
    }
}

// V^T per head: g_qkv V region [SEQ, HD] (stride E3) -> g_vt [HD, SEQ]
__global__ void transpose_v() {
    __shared__ float t[32][33];
    int bh2 = blockIdx.z, b = bh2 >> 4, h = bh2 & 15;
    const float* in = g_qkv + (size_t)b * SEQ * E3 + 2 * EMB + h * HD;
    __nv_bfloat16* oh = g_vt_hi + (size_t)bh2 * HD * SEQ;
    __nv_bfloat16* ol = g_vt_lo + (size_t)bh2 * HD * SEQ;
    int c0 = blockIdx.x * 32, r0 = blockIdx.y * 32;
    int tx = threadIdx.x, ty = threadIdx.y;
#pragma unroll
    for (int j = 0; j < 32; j += 8)
        t[ty + j][tx] = in[(size_t)(r0 + ty + j) * E3 + c0 + tx];
    __syncthreads();
#pragma unroll
    for (int j = 0; j < 32; j += 8) {
        float v = t[tx][ty + j];
        uint32_t bits = __float_as_uint(v);
        __nv_bfloat16 h = __ushort_as_bfloat16((unsigned short)(bits >> 16));
        __nv_bfloat16 l = __float2bfloat16(v - __uint_as_float(bits & 0xFFFF0000u));
        size_t o = (size_t)(c0 + ty + j) * SEQ + r0 + tx;
        oh[o] = h; ol[o] = l;
    }
}

// ===========================================================================
__global__ __launch_bounds__(256) void softmax_kernel(float* __restrict__ P) {
    float* p = P + (size_t)blockIdx.x * SEQ;
    const int tid = threadIdx.x;
    float4* p4 = reinterpret_cast<float4*>(p);
    float4 v0 = p4[tid];
    float4 v1 = p4[tid + 256];
    float m = fmaxf(fmaxf(fmaxf(v0.x, v0.y), fmaxf(v0.z, v0.w)),
                    fmaxf(fmaxf(v1.x, v1.y), fmaxf(v1.z, v1.w)));
    __shared__ float red[256];
    red[tid] = m; __syncthreads();
    for (int s = 128; s > 0; s >>= 1) {
        if (tid < s) red[tid] = fmaxf(red[tid], red[tid + s]);
        __syncthreads();
    }
    float rmax = red[0];
    __syncthreads();
    v0.x = __expf(v0.x - rmax); v0.y = __expf(v0.y - rmax);
    v0.z = __expf(v0.z - rmax); v0.w = __expf(v0.w - rmax);
    v1.x = __expf(v1.x - rmax); v1.y = __expf(v1.y - rmax);
    v1.z = __expf(v1.z - rmax); v1.w = __expf(v1.w - rmax);
    float ssum = v0.x + v0.y + v0.z + v0.w + v1.x + v1.y + v1.z + v1.w;
    red[tid] = ssum; __syncthreads();
    for (int s = 128; s > 0; s >>= 1) {
        if (tid < s) red[tid] += red[tid + s];
        __syncthreads();
    }
    float inv = 1.0f / red[0];
    v0.x *= inv; v0.y *= inv; v0.z *= inv; v0.w *= inv;
    v1.x *= inv; v1.y *= inv; v1.z *= inv; v1.w *= inv;
    p4[tid] = v0;
    p4[tid + 256] = v1;
}

// ===========================================================================
extern "C" void kernel_launch(void* const* d_in, const int* in_sizes, int n_in,
                              void* d_out, int out_size)
{
    (void)in_sizes; (void)n_in; (void)out_size;
    const float* hidden  = (const float*)d_in[0];
    const float* w_fused = (const float*)d_in[1];
    const float* w_proj  = (const float*)d_in[2];
    const float* b_proj  = (const float*)d_in[3];

    float* out   = (float*)d_out;
    float* attnw = out + (size_t)ROWS * EMB;

    cudaFuncSetAttribute(gemm_qkv,    cudaFuncAttributeMaxDynamicSharedMemorySize, SM_TOTAL);
    cudaFuncSetAttribute(gemm_scores, cudaFuncAttributeMaxDynamicSharedMemorySize, SM_TOTAL);
    cudaFuncSetAttribute(gemm_pv,     cudaFuncAttributeMaxDynamicSharedMemorySize, SM_TOTAL);
    cudaFuncSetAttribute(gemm_proj,   cudaFuncAttributeMaxDynamicSharedMemorySize, SM_TOTAL);

    __nv_bfloat16 *wfh, *wfl, *wph, *wpl;
    cudaGetSymbolAddress((void**)&wfh, g_wfT_hi);
    cudaGetSymbolAddress((void**)&wfl, g_wfT_lo);
    cudaGetSymbolAddress((void**)&wph, g_wpT_hi);
    cudaGetSymbolAddress((void**)&wpl, g_wpT_lo);

    // weight transposes + splits
    transpose_hl<<<dim3(E3 / 32, EMB / 32), dim3(32, 8)>>>(w_fused, EMB, E3, wfh, wfl);
    transpose_hl<<<dim3(EMB / 32, EMB / 32), dim3(32, 8)>>>(w_proj, EMB, EMB, wph, wpl);

    // 1) qkv = hidden @ w_fused
    gemm_qkv<<<dim3(E3 / 128, ROWS / 128), 256, SM_TOTAL>>>(hidden);

    // V^T split per head
    transpose_v<<<dim3(HD / 32, SEQ / 32, BSZ * NH), dim3(32, 8)>>>();

    // 2) scores -> attn_weights region
    gemm_scores<<<dim3(SEQ / 128, SEQ / 128, BSZ * NH), 256, SM_TOTAL>>>(attnw);

    // 3) softmax in place
    softmax_kernel<<<BSZ * NH * SEQ, 256>>>(attnw);

    // 4) attn_out = P @ V
    gemm_pv<<<dim3(1, SEQ / 128, BSZ * NH), 256, SM_TOTAL>>>(attnw);

    // 5) out = attn_out @ w_proj + b_proj
    gemm_proj<<<dim3(EMB / 128, ROWS / 128), 256, SM_TOTAL>>>(out, b_proj);
}